// round 2
// baseline (speedup 1.0000x reference)
#include <cuda_runtime.h>

#define TPB 256
#define RPT 4
#define NB  5
#define BLK_FLOATS (TPB * RPT * NB)   // 5120 floats / block (1024 rows)
#define BLK_F4     (BLK_FLOATS / 4)   // 1280 float4

__device__ __forceinline__ float f_ex2(float x){ float y; asm("ex2.approx.ftz.f32 %0, %1;" : "=f"(y) : "f"(x)); return y; }
__device__ __forceinline__ float f_lg2(float x){ float y; asm("lg2.approx.ftz.f32 %0, %1;" : "=f"(y) : "f"(x)); return y; }
__device__ __forceinline__ float f_rcp(float x){ float y; asm("rcp.approx.ftz.f32 %0, %1;" : "=f"(y) : "f"(x)); return y; }
__device__ __forceinline__ float f_rsq(float x){ float y; asm("rsqrt.approx.ftz.f32 %0, %1;" : "=f"(y) : "f"(x)); return y; }

__global__ __launch_bounds__(TPB, 2)
void klproj_kernel(const float* __restrict__ x,
                   const float* __restrict__ W,
                   const float* __restrict__ b,
                   float* __restrict__ out,
                   int nrows)
{
    __shared__ float sx[BLK_FLOATS];   // 20KB staging (input, then output)
    __shared__ float swb[32];

    const int tid   = threadIdx.x;
    const int fbase = blockIdx.x * BLK_FLOATS;          // max ~10.5M, fits int
    const int total = nrows * NB;
    const bool full = (fbase + BLK_FLOATS) <= total;

    if (tid < 30) swb[tid] = (tid < 25) ? W[tid] : b[tid - 25];

    // ---- stage input: 5 coalesced float4 loads/thread ----
    if (full) {
        const float4* g4 = reinterpret_cast<const float4*>(x + fbase);
        float4*       s4 = reinterpret_cast<float4*>(sx);
        #pragma unroll
        for (int k = 0; k < 5; k++) s4[tid + k * TPB] = g4[tid + k * TPB];
    }
    __syncthreads();

    // W/b into registers (amortized over 4 rows)
    float w[25], bb[5];
    #pragma unroll
    for (int i = 0; i < 25; i++) w[i] = swb[i];
    #pragma unroll
    for (int i = 0; i < 5;  i++) bb[i] = swb[25 + i];

    // ---- gather my 4 rows (5x LDS.128 @ tid*80B: conflict-free) ----
    float v[20];
    if (full) {
        #pragma unroll
        for (int k = 0; k < 5; k++) {
            float4 t = *reinterpret_cast<const float4*>(&sx[tid * 20 + k * 4]);
            v[k*4+0] = t.x; v[k*4+1] = t.y; v[k*4+2] = t.z; v[k*4+3] = t.w;
        }
    } else {
        const int rowbase = fbase / NB + tid * RPT;
        #pragma unroll
        for (int r = 0; r < RPT; r++) {
            int row = rowbase + r;
            #pragma unroll
            for (int j = 0; j < NB; j++)
                v[r*5 + j] = (row < nrows) ? x[row * NB + j] : 1.0f;
        }
    }
    __syncthreads();

    const float LOG2_5 = 2.3219280948873623f;
    const float EPS2   = 0.14426950408889634f;   // 0.1 / ln2
    const float LN2    = 0.6931471805599453f;

    // ---- compute 4 rows in place (p overwrites x in v[]) ----
    #pragma unroll
    for (int r = 0; r < RPT; r++) {
        float q[NB];
        float S = 0.f, Q2 = 0.f;
        #pragma unroll
        for (int j = 0; j < NB; j++) {
            float acc = bb[j];
            #pragma unroll
            for (int k = 0; k < NB; k++) acc = fmaf(v[r*5 + k], w[j*5 + k], acc);
            q[j] = acc;
            S  += acc;
            Q2  = fmaf(acc, acc, Q2);
        }
        float rS = f_rcp(S);

        // Cheap sufficient feasibility: KL(p||u) <= ln(5*Q2/S^2); e^0.1 ~= 1.10517092
        if (5.0f * Q2 <= 1.1051709f * S * S) {
            #pragma unroll
            for (int j = 0; j < NB; j++) v[r*5 + j] = q[j] * rS;
        } else {
            // exact test + Newton fallback (rare)
            float L[NB];
            float A1 = 0.f;
            #pragma unroll
            for (int j = 0; j < NB; j++) { L[j] = f_lg2(q[j]); A1 = fmaf(L[j], q[j], A1); }
            float KL1 = fmaf(A1, rS, LOG2_5) - f_lg2(S);
            if (KL1 <= EPS2) {
                #pragma unroll
                for (int j = 0; j < NB; j++) v[r*5 + j] = q[j] * rS;
            } else {
                float t = f_rsq(KL1 * 6.9314718055994531f);   // sqrt(EPS2/KL1)
                t = fminf(fmaxf(t, 1e-3f), 0.999f);
                #pragma unroll
                for (int it = 0; it < 5; ++it) {
                    float Se = 0.f, A = 0.f, B = 0.f;
                    #pragma unroll
                    for (int j = 0; j < NB; j++) {
                        float z  = t * L[j];
                        float e  = f_ex2(z);
                        float ze = z * e;
                        Se += e;  A += ze;  B = fmaf(z, ze, B);
                    }
                    float rSe   = f_rcp(Se);
                    float fval  = fmaf(A, rSe, LOG2_5 - EPS2) - f_lg2(Se);
                    float denom = LN2 * rSe * (B - A * A * rSe);
                    t = t - fval * t * f_rcp(denom);
                    t = fminf(fmaxf(t, 1e-4f), 1.0f);
                }
                float Se = 0.f, e[NB];
                #pragma unroll
                for (int j = 0; j < NB; j++) { e[j] = f_ex2(t * L[j]); Se += e[j]; }
                float rSe = f_rcp(Se);
                #pragma unroll
                for (int j = 0; j < NB; j++) v[r*5 + j] = e[j] * rSe;
            }
        }
    }

    // ---- stage output back, coalesced float4 stores ----
    __syncthreads();   // all input reads done; safe to overwrite sx
    if (full) {
        #pragma unroll
        for (int k = 0; k < 5; k++) {
            float4 t = make_float4(v[k*4+0], v[k*4+1], v[k*4+2], v[k*4+3]);
            *reinterpret_cast<float4*>(&sx[tid * 20 + k * 4]) = t;
        }
        __syncthreads();
        float4*       o4 = reinterpret_cast<float4*>(out + fbase);
        const float4* s4 = reinterpret_cast<const float4*>(sx);
        #pragma unroll
        for (int k = 0; k < 5; k++) o4[tid + k * TPB] = s4[tid + k * TPB];
    } else {
        const int rowbase = fbase / NB + tid * RPT;
        for (int r = 0; r < RPT; r++) {
            int row = rowbase + r;
            if (row < nrows)
                for (int j = 0; j < NB; j++) out[row * NB + j] = v[r*5 + j];
        }
    }
}

extern "C" void kernel_launch(void* const* d_in, const int* in_sizes, int n_in,
                              void* d_out, int out_size)
{
    const float* x = (const float*)d_in[0];
    const float* W = (const float*)d_in[1];
    const float* b = (const float*)d_in[2];
    if (n_in >= 3 && in_sizes[1] == NB && in_sizes[2] == NB * NB) {
        const float* tmp = W; W = b; b = tmp;
    }
    float* out = (float*)d_out;
    int nrows  = in_sizes[0] / NB;
    int rows_per_block = TPB * RPT;
    int blocks = (nrows + rows_per_block - 1) / rows_per_block;
    klproj_kernel<<<blocks, TPB>>>(x, W, b, out, nrows);
}

// round 3
// speedup vs baseline: 1.4176x; 1.4176x over previous
#include <cuda_runtime.h>

#define TPB 256
#define NB  5
#define TILE_ROWS   TPB                  // 256 rows per tile
#define TILE_FLOATS (TILE_ROWS * NB)     // 1280 floats
#define TILE_F4     (TILE_FLOATS / 4)    // 320 float4
#define NBLOCKS     888                  // 148 SMs * 6

__device__ __forceinline__ float f_ex2(float x){ float y; asm("ex2.approx.ftz.f32 %0, %1;" : "=f"(y) : "f"(x)); return y; }
__device__ __forceinline__ float f_lg2(float x){ float y; asm("lg2.approx.ftz.f32 %0, %1;" : "=f"(y) : "f"(x)); return y; }
__device__ __forceinline__ float f_rcp(float x){ float y; asm("rcp.approx.ftz.f32 %0, %1;" : "=f"(y) : "f"(x)); return y; }
__device__ __forceinline__ float f_rsq(float x){ float y; asm("rsqrt.approx.ftz.f32 %0, %1;" : "=f"(y) : "f"(x)); return y; }

__device__ __forceinline__ void solve_row(const float* __restrict__ swb,
                                          const float xv[NB], float p[NB])
{
    const float LOG2_5 = 2.3219280948873623f;
    const float EPS2   = 0.14426950408889634f;   // 0.1 / ln2
    const float LN2    = 0.6931471805599453f;

    float q[NB];
    float S = 0.f, Q2 = 0.f;
    #pragma unroll
    for (int j = 0; j < NB; j++) {
        float acc = swb[25 + j];
        #pragma unroll
        for (int k = 0; k < NB; k++) acc = fmaf(xv[k], swb[j * NB + k], acc);
        q[j] = acc;
        S  += acc;
        Q2  = fmaf(acc, acc, Q2);
    }
    float rS = f_rcp(S);

    // Sufficient feasibility: KL(p||u) <= ln(5*Q2/S^2); e^0.1 = 1.10517092
    if (5.0f * Q2 <= 1.1051709f * S * S) {
        #pragma unroll
        for (int j = 0; j < NB; j++) p[j] = q[j] * rS;
        return;
    }
    // exact test (rare)
    float L[NB], A1 = 0.f;
    #pragma unroll
    for (int j = 0; j < NB; j++) { L[j] = f_lg2(q[j]); A1 = fmaf(L[j], q[j], A1); }
    float KL1 = fmaf(A1, rS, LOG2_5) - f_lg2(S);
    if (KL1 <= EPS2) {
        #pragma unroll
        for (int j = 0; j < NB; j++) p[j] = q[j] * rS;
        return;
    }
    // Newton on f(t) = KL2(t) - EPS2 (very rare)
    float t = f_rsq(KL1 * 6.9314718055994531f);          // sqrt(EPS2/KL1)
    t = fminf(fmaxf(t, 1e-3f), 0.999f);
    #pragma unroll
    for (int it = 0; it < 5; ++it) {
        float Se = 0.f, A = 0.f, B = 0.f;
        #pragma unroll
        for (int j = 0; j < NB; j++) {
            float z  = t * L[j];
            float e  = f_ex2(z);
            float ze = z * e;
            Se += e;  A += ze;  B = fmaf(z, ze, B);
        }
        float rSe   = f_rcp(Se);
        float fval  = fmaf(A, rSe, LOG2_5 - EPS2) - f_lg2(Se);
        float denom = LN2 * rSe * (B - A * A * rSe);
        t = t - fval * t * f_rcp(denom);
        t = fminf(fmaxf(t, 1e-4f), 1.0f);
    }
    float Se = 0.f, e[NB];
    #pragma unroll
    for (int j = 0; j < NB; j++) { e[j] = f_ex2(t * L[j]); Se += e[j]; }
    float rSe = f_rcp(Se);
    #pragma unroll
    for (int j = 0; j < NB; j++) p[j] = e[j] * rSe;
}

__global__ __launch_bounds__(TPB)
void klproj_kernel(const float* __restrict__ x,
                   const float* __restrict__ W,
                   const float* __restrict__ b,
                   float* __restrict__ out,
                   int nrows, int ntiles)
{
    __shared__ float sin_[TILE_FLOATS];  // input staging
    __shared__ float sout[TILE_FLOATS];  // output staging
    __shared__ float swb[32];

    const int tid   = threadIdx.x;
    const int total = nrows * NB;

    if (tid < 30) swb[tid] = (tid < 25) ? W[tid] : b[tid - 25];

    const bool has2 = tid < (TILE_F4 - TPB);   // 320-256 = 64 extra float4

    // ---- prefetch first tile ----
    int t = blockIdx.x;
    float4 r0, r1;
    bool pf = (t < ntiles) && ((t * TILE_FLOATS + TILE_FLOATS) <= total);
    if (pf) {
        const float4* g4 = reinterpret_cast<const float4*>(x) + (size_t)t * TILE_F4;
        r0 = g4[tid];
        if (has2) r1 = g4[tid + TPB];
    }
    __syncthreads();   // swb visible

    for (; t < ntiles; t += NBLOCKS) {
        const int fbase = t * TILE_FLOATS;
        const bool full = (fbase + TILE_FLOATS) <= total;
        const int tn = t + NBLOCKS;
        const bool pfn = (tn < ntiles) && ((tn * TILE_FLOATS + TILE_FLOATS) <= total);

        if (full) {
            // stage prefetched tile
            float4* s4 = reinterpret_cast<float4*>(sin_);
            s4[tid] = r0;
            if (has2) s4[tid + TPB] = r1;
            __syncthreads();

            // issue next tile's loads immediately (hide L2 latency behind compute)
            if (pfn) {
                const float4* g4 = reinterpret_cast<const float4*>(x) + (size_t)tn * TILE_F4;
                r0 = g4[tid];
                if (has2) r1 = g4[tid + TPB];
            }

            // gather my row (stride-5 scalar LDS: conflict-free)
            float xv[NB], p[NB];
            #pragma unroll
            for (int j = 0; j < NB; j++) xv[j] = sin_[tid * NB + j];

            solve_row(swb, xv, p);

            #pragma unroll
            for (int j = 0; j < NB; j++) sout[tid * NB + j] = p[j];
            __syncthreads();

            // coalesced write-back
            const float4* so4 = reinterpret_cast<const float4*>(sout);
            float4*       o4  = reinterpret_cast<float4*>(out) + (size_t)t * TILE_F4;
            o4[tid] = so4[tid];
            if (has2) o4[tid + TPB] = so4[tid + TPB];
        } else {
            // partial tail tile: direct per-row path (no staging)
            int row = fbase / NB + tid;
            if (row < nrows) {
                float xv[NB], p[NB];
                #pragma unroll
                for (int j = 0; j < NB; j++) xv[j] = x[(size_t)row * NB + j];
                solve_row(swb, xv, p);
                #pragma unroll
                for (int j = 0; j < NB; j++) out[(size_t)row * NB + j] = p[j];
            }
            __syncthreads();
            if (pfn) {
                const float4* g4 = reinterpret_cast<const float4*>(x) + (size_t)tn * TILE_F4;
                r0 = g4[tid];
                if (has2) r1 = g4[tid + TPB];
            }
            __syncthreads();
        }
    }
}

extern "C" void kernel_launch(void* const* d_in, const int* in_sizes, int n_in,
                              void* d_out, int out_size)
{
    const float* x = (const float*)d_in[0];
    const float* W = (const float*)d_in[1];
    const float* b = (const float*)d_in[2];
    if (n_in >= 3 && in_sizes[1] == NB && in_sizes[2] == NB * NB) {
        const float* tmp = W; W = b; b = tmp;
    }
    float* out = (float*)d_out;
    int nrows  = in_sizes[0] / NB;
    int ntiles = (nrows + TILE_ROWS - 1) / TILE_ROWS;
    int blocks = (ntiles < NBLOCKS) ? ntiles : NBLOCKS;
    klproj_kernel<<<blocks, TPB>>>(x, W, b, out, nrows, ntiles);
}